// round 2
// baseline (speedup 1.0000x reference)
#include <cuda_runtime.h>

// GCN_18760417149681 — fully linear GraphSAGE collapse.
// out[m] = inv[m]*(SB[m] + SG[m]) + xs[m] + (deg[m]>0)*CB + C2
// SA/SG = segment_sum(xp/xg over edges), SB = segment_sum(t[src]),
// t = inv*SA, xp = x.p, xg = x.g, xs = x.s; p,g,s are 64-vectors
// precomputed from the weights (exact collapse: the network is linear).

#define NMAX 100000
#define EMAX 1600000
#define NFEAT 64
#define NHID 128

// ---- precomputed small vectors / consts ----
__device__ __align__(16) float g_P[NFEAT];
__device__ __align__(16) float g_G[NFEAT];
__device__ __align__(16) float g_S[NFEAT];
__device__ float g_C[2];   // [0]=cb (gated by deg>0), [1]=c2 (always)

// ---- edge decode ----
__device__ int g_is64;           // 1 if edge_idx buffer is int64, else int32
__device__ int g_SRC[EMAX];
__device__ int g_DST[EMAX];

// ---- per-node scratch ----
__device__ float2 g_XPG[NMAX];   // (xp, xg)
__device__ float  g_XS[NMAX];
__device__ float2 g_SAG[NMAX];   // (SA, SG) atomic accumulators
__device__ float  g_SB[NMAX];
__device__ float  g_T[NMAX];
__device__ float  g_DEG[NMAX];
__device__ float  g_INV[NMAX];

// ===================== dtype sniff =====================
// int64 little-endian with indices < 2^31  =>  all odd 32-bit words are 0.
__global__ void k_sniff(const int* __restrict__ ei32, int E)
{
    if (threadIdx.x == 0) {
        int odd_nonzero = 0;
        // sample 64 odd words spread across the buffer (2E int32 words if int32,
        // 4E words if int64 — sample within first 2E words, valid either way)
        for (int k = 0; k < 64; k++) {
            long long pos = 1 + (long long)k * ((2LL * E - 2) / 64);
            pos |= 1;  // force odd
            if (ei32[pos] != 0) odd_nonzero++;
        }
        g_is64 = (odd_nonzero == 0) ? 1 : 0;
    }
}

// ===================== edge decode + clamp =====================
__global__ void k_decode(const int* __restrict__ ei32, int E, int N)
{
    int e = blockIdx.x * blockDim.x + threadIdx.x;
    if (e >= E) return;
    int is64 = g_is64;
    int s, d;
    if (is64) {
        s = ei32[2LL * e];
        d = ei32[2LL * ((long long)E + e)];
    } else {
        s = ei32[e];
        d = ei32[E + e];
    }
    // clamp for safety (no-op on valid data)
    s = min(max(s, 0), N - 1);
    d = min(max(d, 0), N - 1);
    g_SRC[e] = s;
    g_DST[e] = d;
}

// ===================== prep: collapse weights =====================
__global__ void k_prep(const float* __restrict__ Wl1, const float* __restrict__ Wr1,
                       const float* __restrict__ b1,
                       const float* __restrict__ Wl2, const float* __restrict__ Wr2,
                       const float* __restrict__ b2,
                       const float* __restrict__ Wfc1, const float* __restrict__ bfc1,
                       const float* __restrict__ Wfc2, const float* __restrict__ bfc2)
{
    __shared__ float sw[NHID], su[NHID], sv[NHID];
    int t = threadIdx.x;  // 0..127

    // w = Wfc1 @ Wfc2    (Wfc1: [128,32] row-major, Wfc2: [32,1])
    float acc = 0.f;
    #pragma unroll
    for (int c = 0; c < 32; c++) acc += Wfc1[t * 32 + c] * Wfc2[c];
    sw[t] = acc;
    __syncthreads();

    // u = Wl2 @ w, v = Wr2 @ w   (row-major [128,128])
    float au = 0.f, av = 0.f;
    #pragma unroll 4
    for (int j = 0; j < NHID; j++) {
        float wv = sw[j];
        au += Wl2[t * NHID + j] * wv;
        av += Wr2[t * NHID + j] * wv;
    }
    su[t] = au; sv[t] = av;
    __syncthreads();

    // p = Wl1@u, g = Wr1@u + Wl1@v, s = Wr1@v   (row-major [64,128])
    if (t < NFEAT) {
        float p = 0.f, g = 0.f, s = 0.f;
        #pragma unroll 4
        for (int j = 0; j < NHID; j++) {
            float wl = Wl1[t * NHID + j];
            float wr = Wr1[t * NHID + j];
            float uj = su[j], vj = sv[j];
            p += wl * uj;
            g += wr * uj + wl * vj;
            s += wr * vj;
        }
        g_P[t] = p; g_G[t] = g; g_S[t] = s;
    }

    if (t == 0) {
        float cb = 0.f, c2 = 0.f;
        for (int j = 0; j < NHID; j++) {
            cb += b1[j] * su[j];
            c2 += b1[j] * sv[j] + b2[j] * sw[j];
        }
        for (int c = 0; c < 32; c++) c2 += bfc1[c] * Wfc2[c];
        c2 += bfc2[0];
        g_C[0] = cb; g_C[1] = c2;
    }
}

// ===================== zero accumulators =====================
__global__ void k_zero(int n)
{
    int i = blockIdx.x * blockDim.x + threadIdx.x;
    if (i < n) {
        g_SAG[i] = make_float2(0.f, 0.f);
        g_SB[i]  = 0.f;
        g_DEG[i] = 0.f;
    }
}

// ===================== node pass A: 3 dots per node =====================
// one warp per node; lane handles 2 consecutive floats.
__global__ void k_passA(const float* __restrict__ x, int n)
{
    int warp = (blockIdx.x * blockDim.x + threadIdx.x) >> 5;
    int lane = threadIdx.x & 31;
    if (warp >= n) return;

    float2 xv = __ldg(((const float2*)x) + (long long)warp * 32 + lane);
    float2 pv = ((const float2*)g_P)[lane];
    float2 gv = ((const float2*)g_G)[lane];
    float2 sv = ((const float2*)g_S)[lane];

    float xp = xv.x * pv.x + xv.y * pv.y;
    float xg = xv.x * gv.x + xv.y * gv.y;
    float xs = xv.x * sv.x + xv.y * sv.y;

    #pragma unroll
    for (int off = 16; off; off >>= 1) {
        xp += __shfl_xor_sync(0xffffffffu, xp, off);
        xg += __shfl_xor_sync(0xffffffffu, xg, off);
        xs += __shfl_xor_sync(0xffffffffu, xs, off);
    }
    if (lane == 0) {
        g_XPG[warp] = make_float2(xp, xg);
        g_XS[warp]  = xs;
    }
}

// ===================== scatter pass 1 =====================
__global__ void k_scatter1(int E)
{
    int e = blockIdx.x * blockDim.x + threadIdx.x;
    if (e >= E) return;
    int src = g_SRC[e];
    int dst = g_DST[e];
    float2 v = g_XPG[src];
    atomicAdd(&g_SAG[dst].x, v.x);
    atomicAdd(&g_SAG[dst].y, v.y);
    atomicAdd(&g_DEG[dst], 1.0f);
}

// ===================== node pass T =====================
__global__ void k_passT(int n)
{
    int i = blockIdx.x * blockDim.x + threadIdx.x;
    if (i < n) {
        float inv = 1.0f / fmaxf(g_DEG[i], 1.0f);
        g_INV[i] = inv;
        g_T[i]   = inv * g_SAG[i].x;
    }
}

// ===================== scatter pass 2 =====================
__global__ void k_scatter2(int E)
{
    int e = blockIdx.x * blockDim.x + threadIdx.x;
    if (e >= E) return;
    atomicAdd(&g_SB[g_DST[e]], g_T[g_SRC[e]]);
}

// ===================== final =====================
__global__ void k_final(float* __restrict__ out, int n)
{
    int i = blockIdx.x * blockDim.x + threadIdx.x;
    if (i < n) {
        float cb = g_C[0], c2 = g_C[1];
        float res = g_INV[i] * (g_SB[i] + g_SAG[i].y) + g_XS[i] + c2;
        if (g_DEG[i] > 0.0f) res += cb;
        out[i] = res;
    }
}

// ===================== launch =====================
extern "C" void kernel_launch(void* const* d_in, const int* in_sizes, int n_in,
                              void* d_out, int out_size)
{
    const float* x    = (const float*)d_in[0];
    const int*   ei32 = (const int*)d_in[1];   // int32 or int64 — sniffed on device
    // d_in[2] = edge_weight (unused by the reference)
    const float* Wl1  = (const float*)d_in[3];
    const float* Wr1  = (const float*)d_in[4];
    const float* b1   = (const float*)d_in[5];
    const float* Wl2  = (const float*)d_in[6];
    const float* Wr2  = (const float*)d_in[7];
    const float* b2   = (const float*)d_in[8];
    const float* Wfc1 = (const float*)d_in[9];
    const float* bfc1 = (const float*)d_in[10];
    const float* Wfc2 = (const float*)d_in[11];
    const float* bfc2 = (const float*)d_in[12];
    float* out = (float*)d_out;

    int N = in_sizes[0] / NFEAT;   // 100000
    int E = in_sizes[2];           // 1600000 (edge_weight element count)

    k_prep<<<1, 128>>>(Wl1, Wr1, b1, Wl2, Wr2, b2, Wfc1, bfc1, Wfc2, bfc2);
    k_sniff<<<1, 32>>>(ei32, E);

    int tb = 256;
    k_decode<<<(E + tb - 1) / tb, tb>>>(ei32, E, N);
    k_zero<<<(N + tb - 1) / tb, tb>>>(N);

    // warp per node -> 8 nodes per 256-thread block
    k_passA<<<(N + 7) / 8, 256>>>(x, N);

    k_scatter1<<<(E + tb - 1) / tb, tb>>>(E);
    k_passT<<<(N + tb - 1) / tb, tb>>>(N);
    k_scatter2<<<(E + tb - 1) / tb, tb>>>(E);
    k_final<<<(N + tb - 1) / tb, tb>>>(out, N);
}

// round 3
// speedup vs baseline: 1.3520x; 1.3520x over previous
#include <cuda_runtime.h>

// GCN_18760417149681 — fully linear GraphSAGE collapse, fused 5-launch version.
// out[m] = inv[m]*(SB[m] + SG[m]) + xs[m] + (deg[m]>0)*CB + C2
// ACC[m] = float4(SA, SG, deg, 0) accumulated with one vector atomic per edge.

#define NMAX 100000
#define NFEAT 64
#define NHID 128

// ---- precomputed small vectors / consts ----
__device__ __align__(16) float g_P[NFEAT];
__device__ __align__(16) float g_G[NFEAT];
__device__ __align__(16) float g_S[NFEAT];
__device__ float g_C[2];   // [0]=cb (gated by deg>0), [1]=c2 (always)
__device__ int   g_is64;   // 1 if edge_idx is int64, else int32

// ---- per-node scratch ----
__device__ __align__(16) float4 g_ACC[NMAX];  // (SA, SG, deg, pad)
__device__ float2 g_XPG[NMAX];                // (xp, xg)
__device__ float  g_XS[NMAX];
__device__ float  g_SB[NMAX];

// ===================== prep: collapse weights + dtype sniff =====================
__global__ void k_prep(const float* __restrict__ Wl1, const float* __restrict__ Wr1,
                       const float* __restrict__ b1,
                       const float* __restrict__ Wl2, const float* __restrict__ Wr2,
                       const float* __restrict__ b2,
                       const float* __restrict__ Wfc1, const float* __restrict__ bfc1,
                       const float* __restrict__ Wfc2, const float* __restrict__ bfc2,
                       const int* __restrict__ ei32, int E)
{
    __shared__ float sw[NHID], su[NHID], sv[NHID];
    int t = threadIdx.x;  // 0..127

    // dtype sniff: int64 little-endian with small indices => odd 32-bit words all 0
    if (t == 0) {
        int odd_nonzero = 0;
        for (int k = 0; k < 64; k++) {
            long long pos = 1 + (long long)k * ((2LL * E - 2) / 64);
            pos |= 1;
            if (ei32[pos] != 0) odd_nonzero++;
        }
        g_is64 = (odd_nonzero == 0) ? 1 : 0;
    }

    // w = Wfc1 @ Wfc2    (Wfc1: [128,32] row-major, Wfc2: [32,1])
    float acc = 0.f;
    #pragma unroll
    for (int c = 0; c < 32; c++) acc += Wfc1[t * 32 + c] * Wfc2[c];
    sw[t] = acc;
    __syncthreads();

    // u = Wl2 @ w, v = Wr2 @ w   (row-major [128,128])
    float au = 0.f, av = 0.f;
    #pragma unroll 4
    for (int j = 0; j < NHID; j++) {
        float wv = sw[j];
        au += Wl2[t * NHID + j] * wv;
        av += Wr2[t * NHID + j] * wv;
    }
    su[t] = au; sv[t] = av;
    __syncthreads();

    // p = Wl1@u, g = Wr1@u + Wl1@v, s = Wr1@v   (row-major [64,128])
    if (t < NFEAT) {
        float p = 0.f, g = 0.f, s = 0.f;
        #pragma unroll 4
        for (int j = 0; j < NHID; j++) {
            float wl = Wl1[t * NHID + j];
            float wr = Wr1[t * NHID + j];
            float uj = su[j], vj = sv[j];
            p += wl * uj;
            g += wr * uj + wl * vj;
            s += wr * vj;
        }
        g_P[t] = p; g_G[t] = g; g_S[t] = s;
    }

    if (t == 0) {
        float cb = 0.f, c2 = 0.f;
        for (int j = 0; j < NHID; j++) {
            cb += b1[j] * su[j];
            c2 += b1[j] * sv[j] + b2[j] * sw[j];
        }
        for (int c = 0; c < 32; c++) c2 += bfc1[c] * Wfc2[c];
        c2 += bfc2[0];
        g_C[0] = cb; g_C[1] = c2;
    }
}

// ===================== pass A: 3 dots per node + zero accumulators =====================
// half-warp (16 lanes) per node; lane covers one float4 (4 feats).
__global__ void __launch_bounds__(256) k_passA(const float* __restrict__ x, int n)
{
    int node = (blockIdx.x * blockDim.x + threadIdx.x) >> 4;
    int lane = threadIdx.x & 15;
    if (node >= n) return;

    float4 xv = __ldg(((const float4*)x) + (long long)node * 16 + lane);
    float4 pv = ((const float4*)g_P)[lane];
    float4 gv = ((const float4*)g_G)[lane];
    float4 sv = ((const float4*)g_S)[lane];

    float xp = xv.x * pv.x + xv.y * pv.y + xv.z * pv.z + xv.w * pv.w;
    float xg = xv.x * gv.x + xv.y * gv.y + xv.z * gv.z + xv.w * gv.w;
    float xs = xv.x * sv.x + xv.y * sv.y + xv.z * sv.z + xv.w * sv.w;

    #pragma unroll
    for (int off = 8; off; off >>= 1) {
        xp += __shfl_xor_sync(0xffffffffu, xp, off);
        xg += __shfl_xor_sync(0xffffffffu, xg, off);
        xs += __shfl_xor_sync(0xffffffffu, xs, off);
    }
    if (lane == 0) {
        g_XPG[node] = make_float2(xp, xg);
        g_XS[node]  = xs;
        g_ACC[node] = make_float4(0.f, 0.f, 0.f, 0.f);
        g_SB[node]  = 0.f;
    }
}

// ===================== scatter pass 1: one float4 atomic per edge =====================
__global__ void __launch_bounds__(256) k_scatter1(const int* __restrict__ ei32, int E)
{
    int e = blockIdx.x * blockDim.x + threadIdx.x;
    if (e >= E) return;
    int src, dst;
    if (g_is64) {
        src = ei32[2LL * e];
        dst = ei32[2LL * ((long long)E + e)];
    } else {
        src = ei32[e];
        dst = ei32[E + e];
    }
    float2 v = g_XPG[src];
    atomicAdd(&g_ACC[dst], make_float4(v.x, v.y, 1.0f, 0.0f));
}

// ===================== scatter pass 2: t computed inline =====================
__global__ void __launch_bounds__(256) k_scatter2(const int* __restrict__ ei32, int E)
{
    int e = blockIdx.x * blockDim.x + threadIdx.x;
    if (e >= E) return;
    int src, dst;
    if (g_is64) {
        src = ei32[2LL * e];
        dst = ei32[2LL * ((long long)E + e)];
    } else {
        src = ei32[e];
        dst = ei32[E + e];
    }
    float4 a = g_ACC[src];
    float t = a.x * __frcp_rn(fmaxf(a.z, 1.0f));
    atomicAdd(&g_SB[dst], t);
}

// ===================== final =====================
__global__ void __launch_bounds__(256) k_final(float* __restrict__ out, int n)
{
    int i = blockIdx.x * blockDim.x + threadIdx.x;
    if (i < n) {
        float cb = g_C[0], c2 = g_C[1];
        float4 a = g_ACC[i];
        float inv = __frcp_rn(fmaxf(a.z, 1.0f));
        float res = inv * (g_SB[i] + a.y) + g_XS[i] + c2;
        if (a.z > 0.0f) res += cb;
        out[i] = res;
    }
}

// ===================== launch =====================
extern "C" void kernel_launch(void* const* d_in, const int* in_sizes, int n_in,
                              void* d_out, int out_size)
{
    const float* x    = (const float*)d_in[0];
    const int*   ei32 = (const int*)d_in[1];   // int32 or int64 — sniffed on device
    // d_in[2] = edge_weight (unused by the reference)
    const float* Wl1  = (const float*)d_in[3];
    const float* Wr1  = (const float*)d_in[4];
    const float* b1   = (const float*)d_in[5];
    const float* Wl2  = (const float*)d_in[6];
    const float* Wr2  = (const float*)d_in[7];
    const float* b2   = (const float*)d_in[8];
    const float* Wfc1 = (const float*)d_in[9];
    const float* bfc1 = (const float*)d_in[10];
    const float* Wfc2 = (const float*)d_in[11];
    const float* bfc2 = (const float*)d_in[12];
    float* out = (float*)d_out;

    int N = in_sizes[0] / NFEAT;   // 100000
    int E = in_sizes[2];           // 1600000 (edge_weight element count)

    k_prep<<<1, 128>>>(Wl1, Wr1, b1, Wl2, Wr2, b2, Wfc1, bfc1, Wfc2, bfc2, ei32, E);

    // half-warp per node -> 16 nodes per 256-thread block
    k_passA<<<(N + 15) / 16, 256>>>(x, N);

    int tb = 256;
    k_scatter1<<<(E + tb - 1) / tb, tb>>>(ei32, E);
    k_scatter2<<<(E + tb - 1) / tb, tb>>>(ei32, E);
    k_final<<<(N + tb - 1) / tb, tb>>>(out, N);
}